// round 4
// baseline (speedup 1.0000x reference)
#include <cuda_runtime.h>
#include <cuda_bf16.h>
#include <math.h>
#include <stdint.h>

#define BB 1024
#define SS 200
#define II 4
#define HH 128
#define SH (SS*HH)          // 25600
#define WS (II*HH*HH)       // 65536

__device__ float g_hat[(size_t)BB * II * SS * HH];   // [b][i][s][h], 419 MB

// ---------------------------------------------------------------------------
// warp-level tensor-core helpers (plain sm_103-legal)
// ---------------------------------------------------------------------------
__device__ __forceinline__ uint32_t smem_u32(const void* p) {
    uint32_t a;
    asm("{ .reg .u64 t; cvta.to.shared.u64 t, %1; cvt.u32.u64 %0, t; }"
        : "=r"(a) : "l"(p));
    return a;
}
__device__ __forceinline__ void ldm4(uint32_t* r, uint32_t addr) {
    asm volatile("ldmatrix.sync.aligned.m8n8.x4.shared.b16 {%0,%1,%2,%3}, [%4];"
        : "=r"(r[0]), "=r"(r[1]), "=r"(r[2]), "=r"(r[3]) : "r"(addr));
}
__device__ __forceinline__ void mma16816(float* c, const uint32_t* a, const uint32_t* b) {
    asm volatile(
        "mma.sync.aligned.m16n8k16.row.col.f32.bf16.bf16.f32 "
        "{%0,%1,%2,%3}, {%4,%5,%6,%7}, {%8,%9}, {%0,%1,%2,%3};"
        : "+f"(c[0]), "+f"(c[1]), "+f"(c[2]), "+f"(c[3])
        : "r"(a[0]), "r"(a[1]), "r"(a[2]), "r"(a[3]), "r"(b[0]), "r"(b[1]));
}

// ---------------------------------------------------------------------------
// Phase 1: bf16-split HMMA GEMM. Block = (btile, jt): M=128, N=64, K=128.
// jt = cap_i*2 + nhalf  (64-col slice of the 512-wide j dimension).
// smem pitch 136 bf16 (272 B) -> ldmatrix conflict-free. 104 KB -> 2 CTA/SM.
// ---------------------------------------------------------------------------
#define PITCH 136
#define AT_B (128 * PITCH * 2)    // 34816
#define BT_B (64  * PITCH * 2)    // 17408
#define A_HI 0
#define A_LO (AT_B)
#define B_HI (2*AT_B)
#define B_LO (2*AT_B + BT_B)
#define SMEM_GEMM (2*AT_B + 2*BT_B)   // 104448

__device__ __forceinline__ uint32_t pack2(__nv_bfloat16 a, __nv_bfloat16 b) {
    __nv_bfloat162 t; t.x = a; t.y = b;
    return *(uint32_t*)&t;
}
__device__ __forceinline__ void split_store(char* hi, char* lo, int row, int k, float4 v) {
    __nv_bfloat16 h0 = __float2bfloat16(v.x), h1 = __float2bfloat16(v.y);
    __nv_bfloat16 h2 = __float2bfloat16(v.z), h3 = __float2bfloat16(v.w);
    __nv_bfloat16 l0 = __float2bfloat16(v.x - __bfloat162float(h0));
    __nv_bfloat16 l1 = __float2bfloat16(v.y - __bfloat162float(h1));
    __nv_bfloat16 l2 = __float2bfloat16(v.z - __bfloat162float(h2));
    __nv_bfloat16 l3 = __float2bfloat16(v.w - __bfloat162float(h3));
    uint32_t off = (uint32_t)row * (PITCH*2) + (uint32_t)k * 2;
    *(uint2*)(hi + off) = make_uint2(pack2(h0, h1), pack2(h2, h3));
    *(uint2*)(lo + off) = make_uint2(pack2(l0, l1), pack2(l2, l3));
}

__global__ __launch_bounds__(256, 2)
void gemm_hat_mma(const float* __restrict__ item, const float* __restrict__ w)
{
    extern __shared__ __align__(16) char smp[];
    const uint32_t sbase = smem_u32(smp);

    const int tid   = threadIdx.x;
    const int wid   = tid >> 5;
    const int lane  = tid & 31;
    const int btile = blockIdx.x >> 3;
    const int jt    = blockIdx.x & 7;        // cap_i = jt>>1, nhalf = jt&1
    const int s     = blockIdx.y;
    const int b0    = btile << 7;
    const int cap_i = jt >> 1;

    // ---- load f32 tiles, split-convert to bf16 hi/lo in smem ----
    const float* ga = item + (size_t)b0 * SH + (size_t)s * HH;
    const float* gw = w + (size_t)s * WS + (size_t)jt * (64 * HH);
    #pragma unroll
    for (int q = 0; q < 8; q++) {                     // A: 128x128
        int idx = q * 512 + tid;                      // two rows' worth per q
        int row = idx >> 5;
        int k4  = (idx & 31) << 2;
        float4 av = *(const float4*)(ga + (size_t)row * SH + k4);
        split_store(smp + A_HI, smp + A_LO, row, k4, av);
        int idx2 = idx + 256;
        int row2 = idx2 >> 5;
        int k42  = (idx2 & 31) << 2;
        float4 av2 = *(const float4*)(ga + (size_t)row2 * SH + k42);
        split_store(smp + A_HI, smp + A_LO, row2, k42, av2);
    }
    #pragma unroll
    for (int q = 0; q < 8; q++) {                     // B: 64x128
        int idx = q * 256 + tid;
        int row = idx >> 5;
        int k4  = (idx & 31) << 2;
        float4 wv = *(const float4*)(gw + row * HH + k4);
        split_store(smp + B_HI, smp + B_LO, row, k4, wv);
    }
    __syncthreads();

    const int mw = (wid & 3) * 32;    // warp M base
    const int nw = (wid >> 2) * 32;   // warp N base (within 64)

    float acc[2][4][4];
    #pragma unroll
    for (int mt = 0; mt < 2; mt++)
        #pragma unroll
        for (int nt = 0; nt < 4; nt++)
            #pragma unroll
            for (int c = 0; c < 4; c++) acc[mt][nt][c] = 0.f;

    #pragma unroll
    for (int ks = 0; ks < 8; ks++) {
        const int k0 = ks * 16;
        uint32_t ah[2][4], al[2][4];
        {
            uint32_t aoff = (uint32_t)(mw + (lane & 15)) * (PITCH*2)
                          + (uint32_t)(k0 + ((lane >> 4) << 3)) * 2;
            ldm4(ah[0], sbase + A_HI + aoff);
            ldm4(ah[1], sbase + A_HI + aoff + 16 * (PITCH*2));
            ldm4(al[0], sbase + A_LO + aoff);
            ldm4(al[1], sbase + A_LO + aoff + 16 * (PITCH*2));
        }
        uint32_t bh[2][4], bl[2][4];
        {
            uint32_t boff = (uint32_t)(nw + ((lane >> 4) << 3) + (lane & 7)) * (PITCH*2)
                          + (uint32_t)(k0 + (((lane >> 3) & 1) << 3)) * 2;
            #pragma unroll
            for (int p = 0; p < 2; p++) {
                ldm4(bh[p], sbase + B_HI + boff + (uint32_t)p * 16 * (PITCH*2));
                ldm4(bl[p], sbase + B_LO + boff + (uint32_t)p * 16 * (PITCH*2));
            }
        }
        #pragma unroll
        for (int mt = 0; mt < 2; mt++)
            #pragma unroll
            for (int nt = 0; nt < 4; nt++) {
                const uint32_t* bhp = &bh[nt >> 1][(nt & 1) * 2];
                const uint32_t* blp = &bl[nt >> 1][(nt & 1) * 2];
                mma16816(acc[mt][nt], ah[mt], bhp);   // hi*hi
                mma16816(acc[mt][nt], ah[mt], blp);   // hi*lo
                mma16816(acc[mt][nt], al[mt], bhp);   // lo*hi
            }
    }

    // ---- epilogue: direct float2 stores ----
    const int g = lane >> 2, t = lane & 3;
    const int hbase = (jt & 1) * 64 + nw;
    #pragma unroll
    for (int mt = 0; mt < 2; mt++) {
        int rowm = mw + mt * 16 + g;
        size_t p0 = ((size_t)(b0 + rowm) * II + cap_i) * SH + (size_t)s * HH + hbase;
        size_t p1 = p0 + (size_t)8 * II * SH;   // rows +8
        #pragma unroll
        for (int nt = 0; nt < 4; nt++) {
            *(float2*)(g_hat + p0 + nt * 8 + 2 * t) =
                make_float2(acc[mt][nt][0], acc[mt][nt][1]);
            *(float2*)(g_hat + p1 + nt * 8 + 2 * t) =
                make_float2(acc[mt][nt][2], acc[mt][nt][3]);
        }
    }
}

// ---------------------------------------------------------------------------
// Phase 2: routing with register-resident hat.
// 512 threads; thread (g = t>>7, h = t&127) holds hat[g*50 .. g*50+49][h] in regs.
// ---------------------------------------------------------------------------
__device__ __forceinline__ float warp_sum(float v) {
    #pragma unroll
    for (int o = 16; o > 0; o >>= 1) v += __shfl_xor_sync(0xffffffffu, v, o);
    return v;
}
__device__ __forceinline__ float warp_max(float v) {
    #pragma unroll
    for (int o = 16; o > 0; o >>= 1) v = fmaxf(v, __shfl_xor_sync(0xffffffffu, v, o));
    return v;
}

#define NSLC 50
#define R_CW    0
#define R_SWT   (R_CW + SS)
#define R_CAPP  (R_SWT + SS)          // 512
#define R_CAP   (R_CAPP + 512)        // 128
#define R_RED   (R_CAP + 128)         // 16
#define R_DP    (R_RED + 16)          // 16 warps x 52
#define SMEM_ROUTE ((R_DP + 16*52) * 4)

__global__ __launch_bounds__(512, 1)
void routing_kernel(const int* __restrict__ mask, float* __restrict__ out)
{
    extern __shared__ __align__(16) float sm[];
    float* cw   = sm + R_CW;
    float* swt  = sm + R_SWT;
    float* capp = sm + R_CAPP;
    float* cap  = sm + R_CAP;
    float* red  = sm + R_RED;
    float* dp   = sm + R_DP;

    const int tid  = threadIdx.x;
    const int lane = tid & 31;
    const int wid  = tid >> 5;
    const int g    = tid >> 7;
    const int h    = tid & 127;
    const int b    = blockIdx.x >> 2;

    // hat slice -> registers (coalesced: 128 consecutive h per s)
    float hv[NSLC];
    {
        const float* src = g_hat + (size_t)blockIdx.x * SH + (size_t)(g * NSLC) * HH + h;
        #pragma unroll
        for (int j = 0; j < NSLC; j++) hv[j] = src[(size_t)j * HH];
    }
    int my_mask = (tid < SS) ? mask[b * SS + tid] : 0;
    if (tid < SS) cw[tid] = 0.f;
    __syncthreads();

    const float NEG_INF = __int_as_float(0xff800000);
    float myh_cap = 0.f;   // cap[h] cached per thread after squash

    for (int it = 0; it < 3; it++) {
        // ---- softmax over all s, then mask ----
        float v = (tid < SS) ? cw[tid] : NEG_INF;
        float wm_ = warp_max(v);
        if (lane == 0) red[wid] = wm_;
        __syncthreads();
        float bm = red[0];
        #pragma unroll
        for (int j = 1; j < 16; j++) bm = fmaxf(bm, red[j]);
        float e = (tid < SS) ? expf(v - bm) : 0.f;
        float ws = warp_sum(e);
        __syncthreads();
        if (lane == 0) red[wid] = ws;
        __syncthreads();
        float Z = 0.f;
        #pragma unroll
        for (int j = 0; j < 16; j++) Z += red[j];
        if (tid < SS) swt[tid] = my_mask ? (e / Z) : 0.f;
        __syncthreads();

        // ---- cap partial: register FMAs over this thread's s-slice ----
        {
            const float* sw = swt + g * NSLC;
            float c = 0.f;
            #pragma unroll
            for (int j = 0; j < NSLC; j++) c = fmaf(sw[j], hv[j], c);
            capp[tid] = c;
        }
        __syncthreads();

        // ---- reduce 4 groups + squash ----
        if (tid < 128) {
            float cv = capp[tid] + capp[tid + 128] + capp[tid + 256] + capp[tid + 384];
            float np = cv * cv;
            float wn = warp_sum(np);
            if (lane == 0) red[wid] = wn;
            capp[tid] = cv;           // stash unsquashed
        }
        __syncthreads();
        {
            float n = red[0] + red[1] + red[2] + red[3];
            float f = n / (1.f + n) * rsqrtf(n + 1e-9f);
            if (tid < 128) cap[tid] = capp[tid] * f;
            __syncthreads();
            myh_cap = cap[h];
        }

        // ---- delta: cw[s] += sum_h hat[s,h]*cap[h]  (unmasked) ----
        if (it < 2) {
            #pragma unroll
            for (int j = 0; j < NSLC; j++) {
                float d = warp_sum(hv[j] * myh_cap);
                if (lane == 0) dp[wid * 52 + j] = d;
            }
            __syncthreads();
            if (tid < SS) {
                int gg = tid / NSLC, jj = tid - gg * NSLC;
                cw[tid] += dp[(4*gg + 0) * 52 + jj] + dp[(4*gg + 1) * 52 + jj]
                         + dp[(4*gg + 2) * 52 + jj] + dp[(4*gg + 3) * 52 + jj];
            }
            __syncthreads();
        }
    }

    if (tid < 128)
        out[(size_t)blockIdx.x * HH + tid] = cap[tid];
}

// ---------------------------------------------------------------------------
extern "C" void kernel_launch(void* const* d_in, const int* in_sizes, int n_in,
                              void* d_out, int out_size)
{
    const float* item = (const float*)d_in[0];
    const int*   mask = (const int*)d_in[1];
    const float* w    = (const float*)d_in[2];
    float*       out  = (float*)d_out;

    cudaFuncSetAttribute(gemm_hat_mma,
                         cudaFuncAttributeMaxDynamicSharedMemorySize, SMEM_GEMM);
    cudaFuncSetAttribute(routing_kernel,
                         cudaFuncAttributeMaxDynamicSharedMemorySize, SMEM_ROUTE);

    dim3 ggrid(64, SS);   // x = btile*8 + jt
    gemm_hat_mma<<<ggrid, 256, SMEM_GEMM>>>(item, w);

    routing_kernel<<<BB * II, 512, SMEM_ROUTE>>>(mask, out);
}

// round 5
// speedup vs baseline: 1.0766x; 1.0766x over previous
#include <cuda_runtime.h>
#include <cuda_bf16.h>
#include <math.h>
#include <stdint.h>

#define BB 1024
#define SS 200
#define II 4
#define HH 128
#define SH (SS*HH)          // 25600
#define WS (II*HH*HH)       // 65536

__device__ float g_hat[(size_t)BB * II * SS * HH];   // [b][i][s][h], 419 MB

// ---------------------------------------------------------------------------
// helpers (plain sm_103-legal PTX only: ldmatrix, mma.sync, mbarrier, cp.async.bulk)
// ---------------------------------------------------------------------------
__device__ __forceinline__ uint32_t smem_u32(const void* p) {
    uint32_t a;
    asm("{ .reg .u64 t; cvta.to.shared.u64 t, %1; cvt.u32.u64 %0, t; }"
        : "=r"(a) : "l"(p));
    return a;
}
__device__ __forceinline__ void ldm4(uint32_t* r, uint32_t addr) {
    asm volatile("ldmatrix.sync.aligned.m8n8.x4.shared.b16 {%0,%1,%2,%3}, [%4];"
        : "=r"(r[0]), "=r"(r[1]), "=r"(r[2]), "=r"(r[3]) : "r"(addr));
}
__device__ __forceinline__ void mma16816(float* c, const uint32_t* a, const uint32_t* b) {
    asm volatile(
        "mma.sync.aligned.m16n8k16.row.col.f32.bf16.bf16.f32 "
        "{%0,%1,%2,%3}, {%4,%5,%6,%7}, {%8,%9}, {%0,%1,%2,%3};"
        : "+f"(c[0]), "+f"(c[1]), "+f"(c[2]), "+f"(c[3])
        : "r"(a[0]), "r"(a[1]), "r"(a[2]), "r"(a[3]), "r"(b[0]), "r"(b[1]));
}
__device__ __forceinline__ void mbar_init(uint32_t mbar, uint32_t cnt) {
    asm volatile("mbarrier.init.shared.b64 [%0], %1;" :: "r"(mbar), "r"(cnt) : "memory");
}
__device__ __forceinline__ void mbar_expect_tx(uint32_t mbar, uint32_t bytes) {
    asm volatile("mbarrier.arrive.expect_tx.shared.b64 _, [%0], %1;"
                 :: "r"(mbar), "r"(bytes) : "memory");
}
__device__ __forceinline__ void mbar_wait(uint32_t mbar, uint32_t parity) {
    asm volatile("{\n\t.reg .pred P;\n\t"
        "W_%=:\n\t"
        "mbarrier.try_wait.parity.acquire.cta.shared::cta.b64 P, [%0], %1, 0x989680;\n\t"
        "@P bra.uni D_%=;\n\t"
        "bra.uni W_%=;\n\t"
        "D_%=:\n\t}" :: "r"(mbar), "r"(parity) : "memory");
}
__device__ __forceinline__ void bulk_g2s(uint32_t dst, const void* src,
                                         uint32_t bytes, uint32_t mbar) {
    asm volatile(
        "cp.async.bulk.shared::cta.global.mbarrier::complete_tx::bytes [%0], [%1], %2, [%3];"
        :: "r"(dst), "l"(src), "r"(bytes), "r"(mbar) : "memory");
}

// ---------------------------------------------------------------------------
// Phase 1: bf16-split HMMA GEMM (unchanged from R4: at its tensor-pipe floor).
// Block = (btile, jt): M=128, N=64, K=128.
// ---------------------------------------------------------------------------
#define PITCH 136
#define AT_B (128 * PITCH * 2)    // 34816
#define BT_B (64  * PITCH * 2)    // 17408
#define A_HI 0
#define A_LO (AT_B)
#define B_HI (2*AT_B)
#define B_LO (2*AT_B + BT_B)
#define SMEM_GEMM (2*AT_B + 2*BT_B)   // 104448

__device__ __forceinline__ uint32_t pack2(__nv_bfloat16 a, __nv_bfloat16 b) {
    __nv_bfloat162 t; t.x = a; t.y = b;
    return *(uint32_t*)&t;
}
__device__ __forceinline__ void split_store(char* hi, char* lo, int row, int k, float4 v) {
    __nv_bfloat16 h0 = __float2bfloat16(v.x), h1 = __float2bfloat16(v.y);
    __nv_bfloat16 h2 = __float2bfloat16(v.z), h3 = __float2bfloat16(v.w);
    __nv_bfloat16 l0 = __float2bfloat16(v.x - __bfloat162float(h0));
    __nv_bfloat16 l1 = __float2bfloat16(v.y - __bfloat162float(h1));
    __nv_bfloat16 l2 = __float2bfloat16(v.z - __bfloat162float(h2));
    __nv_bfloat16 l3 = __float2bfloat16(v.w - __bfloat162float(h3));
    uint32_t off = (uint32_t)row * (PITCH*2) + (uint32_t)k * 2;
    *(uint2*)(hi + off) = make_uint2(pack2(h0, h1), pack2(h2, h3));
    *(uint2*)(lo + off) = make_uint2(pack2(l0, l1), pack2(l2, l3));
}

__global__ __launch_bounds__(256, 2)
void gemm_hat_mma(const float* __restrict__ item, const float* __restrict__ w)
{
    extern __shared__ __align__(16) char smp[];
    const uint32_t sbase = smem_u32(smp);

    const int tid   = threadIdx.x;
    const int wid   = tid >> 5;
    const int lane  = tid & 31;
    const int btile = blockIdx.x >> 3;
    const int jt    = blockIdx.x & 7;
    const int s     = blockIdx.y;
    const int b0    = btile << 7;
    const int cap_i = jt >> 1;

    const float* ga = item + (size_t)b0 * SH + (size_t)s * HH;
    const float* gw = w + (size_t)s * WS + (size_t)jt * (64 * HH);
    #pragma unroll
    for (int q = 0; q < 8; q++) {
        int idx = q * 512 + tid;
        int row = idx >> 5;
        int k4  = (idx & 31) << 2;
        float4 av = *(const float4*)(ga + (size_t)row * SH + k4);
        split_store(smp + A_HI, smp + A_LO, row, k4, av);
        int idx2 = idx + 256;
        int row2 = idx2 >> 5;
        int k42  = (idx2 & 31) << 2;
        float4 av2 = *(const float4*)(ga + (size_t)row2 * SH + k42);
        split_store(smp + A_HI, smp + A_LO, row2, k42, av2);
    }
    #pragma unroll
    for (int q = 0; q < 8; q++) {
        int idx = q * 256 + tid;
        int row = idx >> 5;
        int k4  = (idx & 31) << 2;
        float4 wv = *(const float4*)(gw + row * HH + k4);
        split_store(smp + B_HI, smp + B_LO, row, k4, wv);
    }
    __syncthreads();

    const int mw = (wid & 3) * 32;
    const int nw = (wid >> 2) * 32;

    float acc[2][4][4];
    #pragma unroll
    for (int mt = 0; mt < 2; mt++)
        #pragma unroll
        for (int nt = 0; nt < 4; nt++)
            #pragma unroll
            for (int c = 0; c < 4; c++) acc[mt][nt][c] = 0.f;

    #pragma unroll
    for (int ks = 0; ks < 8; ks++) {
        const int k0 = ks * 16;
        uint32_t ah[2][4], al[2][4];
        {
            uint32_t aoff = (uint32_t)(mw + (lane & 15)) * (PITCH*2)
                          + (uint32_t)(k0 + ((lane >> 4) << 3)) * 2;
            ldm4(ah[0], sbase + A_HI + aoff);
            ldm4(ah[1], sbase + A_HI + aoff + 16 * (PITCH*2));
            ldm4(al[0], sbase + A_LO + aoff);
            ldm4(al[1], sbase + A_LO + aoff + 16 * (PITCH*2));
        }
        uint32_t bh[2][4], bl[2][4];
        {
            uint32_t boff = (uint32_t)(nw + ((lane >> 4) << 3) + (lane & 7)) * (PITCH*2)
                          + (uint32_t)(k0 + (((lane >> 3) & 1) << 3)) * 2;
            #pragma unroll
            for (int p = 0; p < 2; p++) {
                ldm4(bh[p], sbase + B_HI + boff + (uint32_t)p * 16 * (PITCH*2));
                ldm4(bl[p], sbase + B_LO + boff + (uint32_t)p * 16 * (PITCH*2));
            }
        }
        #pragma unroll
        for (int mt = 0; mt < 2; mt++)
            #pragma unroll
            for (int nt = 0; nt < 4; nt++) {
                const uint32_t* bhp = &bh[nt >> 1][(nt & 1) * 2];
                const uint32_t* blp = &bl[nt >> 1][(nt & 1) * 2];
                mma16816(acc[mt][nt], ah[mt], bhp);
                mma16816(acc[mt][nt], ah[mt], blp);
                mma16816(acc[mt][nt], al[mt], bhp);
            }
    }

    const int g = lane >> 2, t = lane & 3;
    const int hbase = (jt & 1) * 64 + nw;
    #pragma unroll
    for (int mt = 0; mt < 2; mt++) {
        int rowm = mw + mt * 16 + g;
        size_t p0 = ((size_t)(b0 + rowm) * II + cap_i) * SH + (size_t)s * HH + hbase;
        size_t p1 = p0 + (size_t)8 * II * SH;
        #pragma unroll
        for (int nt = 0; nt < 4; nt++) {
            *(float2*)(g_hat + p0 + nt * 8 + 2 * t) =
                make_float2(acc[mt][nt][0], acc[mt][nt][1]);
            *(float2*)(g_hat + p1 + nt * 8 + 2 * t) =
                make_float2(acc[mt][nt][2], acc[mt][nt][3]);
        }
    }
}

// ---------------------------------------------------------------------------
// Phase 2: persistent double-buffered routing.
// 148 CTAs x 512 threads; cp.async.bulk streams next hat tile while computing.
// ---------------------------------------------------------------------------
__device__ __forceinline__ float warp_sum(float v) {
    #pragma unroll
    for (int o = 16; o > 0; o >>= 1) v += __shfl_xor_sync(0xffffffffu, v, o);
    return v;
}
__device__ __forceinline__ float warp_max(float v) {
    #pragma unroll
    for (int o = 16; o > 0; o >>= 1) v = fmaxf(v, __shfl_xor_sync(0xffffffffu, v, o));
    return v;
}

#define NBLK 148
#define HATB (SS*HH*4)                // 102400 bytes per tile
#define R_BUF0 0
#define R_BUF1 (SS*HH)                // 25600
#define R_CAPP (2*SS*HH)              // 51200 : [16][128]
#define R_CW   (R_CAPP + 2048)        // 53248
#define R_SWT  (R_CW + SS)            // 53448
#define R_CAP  (R_SWT + SS)           // 53648
#define R_RED  (R_CAP + 128)          // 53776
#define R_F32  (R_RED + 16)           // 53792 floats = 215168 B (16B aligned)
#define R_MB   (R_F32 * 4)            // mbar bytes offset
#define SMEM_ROUTE (R_MB + 32)

__global__ __launch_bounds__(512, 1)
void routing_kernel(const int* __restrict__ mask, float* __restrict__ out)
{
    extern __shared__ __align__(16) float sm[];
    const uint32_t sb = smem_u32(sm);

    float*  cw    = sm + R_CW;
    float*  swt   = sm + R_SWT;
    float4* capp4 = (float4*)(sm + R_CAPP);
    float4* cap4  = (float4*)(sm + R_CAP);
    float*  capf  = sm + R_CAP;
    float*  red   = sm + R_RED;
    const uint32_t mb0 = sb + R_MB;
    const uint32_t mb1 = mb0 + 8;

    const int tid  = threadIdx.x;
    const int lane = tid & 31;
    const int wid  = tid >> 5;

    if (tid == 0) {
        mbar_init(mb0, 1);
        mbar_init(mb1, 1);
        asm volatile("fence.proxy.async.shared::cta;" ::: "memory");
    }
    __syncthreads();

    const float NEG_INF = __int_as_float(0xff800000);
    uint32_t ph[2] = {0u, 0u};

    // prologue: stage first item
    int w0 = blockIdx.x;
    if (w0 < BB * II && tid == 0) {
        mbar_expect_tx(mb0, HATB);
        bulk_g2s(sb + R_BUF0 * 4, g_hat + (size_t)w0 * SH, HATB, mb0);
    }

    int n = 0;
    for (int w = w0; w < BB * II; w += NBLK, n++) {
        const int slot = n & 1;
        const uint32_t mb_cur = slot ? mb1 : mb0;

        // mask + cw init for this item (independent of hat buffers)
        int my_mask = (tid < SS) ? mask[(w >> 2) * SS + tid] : 0;
        if (tid < SS) cw[tid] = 0.f;

        // wait for current tile
        mbar_wait(mb_cur, ph[slot]);
        ph[slot] ^= 1;

        // stage next tile into the other slot (freed by end-of-item sync below)
        int wn = w + NBLK;
        if (wn < BB * II && tid == 0) {
            const uint32_t mb_nx = slot ? mb0 : mb1;
            mbar_expect_tx(mb_nx, HATB);
            bulk_g2s(sb + (slot ? R_BUF0 : R_BUF1) * 4,
                     g_hat + (size_t)wn * SH, HATB, mb_nx);
        }
        __syncthreads();   // cw/swt visible; everyone past wait

        float4* hs4 = (float4*)(sm + (slot ? R_BUF1 : R_BUF0));

        for (int it = 0; it < 3; it++) {
            // softmax over all s (mask applied after normalization)
            float v = (tid < SS) ? cw[tid] : NEG_INF;
            float wm_ = warp_max(v);
            if (lane == 0) red[wid] = wm_;
            __syncthreads();
            float bm = red[0];
            #pragma unroll
            for (int j = 1; j < 16; j++) bm = fmaxf(bm, red[j]);
            float e = (tid < SS) ? expf(v - bm) : 0.f;
            float ws = warp_sum(e);
            __syncthreads();
            if (lane == 0) red[wid] = ws;
            __syncthreads();
            float Z = 0.f;
            #pragma unroll
            for (int j = 0; j < 16; j++) Z += red[j];
            if (tid < SS) swt[tid] = my_mask ? (e / Z) : 0.f;
            __syncthreads();

            // cap = sum_s sw[s] * hat[s,:]
            {
                int g = tid & 31, sl = tid >> 5;
                float4 acc = make_float4(0.f, 0.f, 0.f, 0.f);
                for (int s2 = sl; s2 < SS; s2 += 16) {
                    float sv = swt[s2];
                    float4 hv = hs4[s2 * 32 + g];
                    acc.x = fmaf(sv, hv.x, acc.x);
                    acc.y = fmaf(sv, hv.y, acc.y);
                    acc.z = fmaf(sv, hv.z, acc.z);
                    acc.w = fmaf(sv, hv.w, acc.w);
                }
                capp4[sl * 32 + g] = acc;
            }
            __syncthreads();

            // reduce + squash (warp 0)
            if (tid < 32) {
                float4 r = make_float4(0.f, 0.f, 0.f, 0.f);
                #pragma unroll
                for (int sl = 0; sl < 16; sl++) {
                    float4 tv = capp4[sl * 32 + tid];
                    r.x += tv.x; r.y += tv.y; r.z += tv.z; r.w += tv.w;
                }
                float np = r.x * r.x + r.y * r.y + r.z * r.z + r.w * r.w;
                float nn = warp_sum(np);
                float f = nn / (1.f + nn) * rsqrtf(nn + 1e-9f);
                cap4[tid] = make_float4(r.x * f, r.y * f, r.z * f, r.w * f);
            }
            __syncthreads();

            // delta: cw[s] += hat[s,:] . cap  (unmasked)
            if (it < 2) {
                float4 cv = cap4[lane];
                for (int s2 = wid; s2 < SS; s2 += 16) {
                    float4 hv = hs4[s2 * 32 + lane];
                    float d = hv.x * cv.x + hv.y * cv.y + hv.z * cv.z + hv.w * cv.w;
                    d = warp_sum(d);
                    if (lane == 0) cw[s2] += d;
                }
                __syncthreads();
            }
        }

        if (tid < 128)
            out[(size_t)w * HH + tid] = capf[tid];
        __syncthreads();   // all reads of this slot done before it is re-staged
    }
}

// ---------------------------------------------------------------------------
extern "C" void kernel_launch(void* const* d_in, const int* in_sizes, int n_in,
                              void* d_out, int out_size)
{
    const float* item = (const float*)d_in[0];
    const int*   mask = (const int*)d_in[1];
    const float* w    = (const float*)d_in[2];
    float*       out  = (float*)d_out;

    cudaFuncSetAttribute(gemm_hat_mma,
                         cudaFuncAttributeMaxDynamicSharedMemorySize, SMEM_GEMM);
    cudaFuncSetAttribute(routing_kernel,
                         cudaFuncAttributeMaxDynamicSharedMemorySize, SMEM_ROUTE);

    dim3 ggrid(64, SS);   // x = btile*8 + jt
    gemm_hat_mma<<<ggrid, 256, SMEM_GEMM>>>(item, w);

    routing_kernel<<<NBLK, 512, SMEM_ROUTE>>>(mask, out);
}